// round 14
// baseline (speedup 1.0000x reference)
#include <cuda_runtime.h>
#include <cuda_fp16.h>
#include <cstdint>

#define B_ANCH 2048
#define P_POS  4
#define D_DIM  256            // K
#define NNEG   32768
#define ALPHA  0.1f
#define EPSN   1e-12f
#define INV_T  20.0f          // 1/temperature
#define K2E    28.85390081777927f   // 20 * log2(e)
#define SHIFT2 8.0f                 // sum exp2(logit2 - 8)

#define MT     128            // anchors per CTA
#define NB     128            // negatives per tile
#define MBLKS  (B_ANCH / MT)  // 16
#define NGRP   18             // grid 16*18 = 288 CTAs
#define NCTAS  (MBLKS * NGRP) // 288
#define STR    272            // smem row stride bytes

#define A_BYTES (MT * STR)          // 34816
#define B_BYTES (NB * STR)          // 34816
#define SMEM_TOTAL (A_BYTES + 2 * B_BYTES)   // 104448 -> occ 2

// ---- scratch ----
__device__ uint8_t g_a8[B_ANCH * D_DIM];      // e4m3
__device__ uint8_t g_n8[NNEG * D_DIM];        // e4m3
__device__ float g_pos[B_ANCH * P_POS];
__device__ float g_part[NGRP * B_ANCH];       // [gp][anchor]
__device__ int   g_ctr;                       // arrival counter (self-resetting)

// ================= helpers =================
__device__ __forceinline__ uint32_t smem_u32(const void* p) {
    uint32_t a;
    asm("{ .reg .u64 t; cvta.to.shared.u64 t, %1; cvt.u32.u64 %0, t; }" : "=r"(a) : "l"(p));
    return a;
}
__device__ __forceinline__ void cp_async16(uint32_t dst, const void* src) {
    asm volatile("cp.async.cg.shared.global [%0], [%1], 16;" :: "r"(dst), "l"(src) : "memory");
}
#define CP_COMMIT() asm volatile("cp.async.commit_group;" ::: "memory")
#define CP_WAIT(n)  asm volatile("cp.async.wait_group %0;" :: "n"(n) : "memory")

__device__ __forceinline__ uint32_t pack_e4m3_4(float x, float y, float z, float w) {
    uint16_t lo, hi;
    asm("cvt.rn.satfinite.e4m3x2.f32 %0, %1, %2;" : "=h"(lo) : "f"(y), "f"(x));
    asm("cvt.rn.satfinite.e4m3x2.f32 %0, %1, %2;" : "=h"(hi) : "f"(w), "f"(z));
    return (uint32_t)lo | ((uint32_t)hi << 16);
}

__device__ __forceinline__ void mma_fp8_h(uint32_t* c, const uint32_t* a,
                                          uint32_t b0, uint32_t b1) {
    asm volatile(
        "mma.sync.aligned.m16n8k32.row.col.f16.e4m3.e4m3.f16 "
        "{%0,%1}, {%2,%3,%4,%5}, {%6,%7}, {%0,%1};\n"
        : "+r"(c[0]), "+r"(c[1])
        : "r"(a[0]), "r"(a[1]), "r"(a[2]), "r"(a[3]), "r"(b0), "r"(b1));
}

__device__ __forceinline__ void ldsm_x4(uint32_t& r0, uint32_t& r1,
                                        uint32_t& r2, uint32_t& r3, uint32_t a) {
    asm volatile("ldmatrix.sync.aligned.m8n8.x4.shared.b16 {%0,%1,%2,%3}, [%4];"
                 : "=r"(r0), "=r"(r1), "=r"(r2), "=r"(r3) : "r"(a));
}

// ============================================================
// Kernel 1: fused prep (R11 layout: warp per task)
// tasks: [0, B+N) normalize, [B+N, B+N+B*P) pos
// ============================================================
__global__ void prep_kernel(const float* __restrict__ anch,
                            const float* __restrict__ pos,
                            const float* __restrict__ neg) {
    int warp = threadIdx.x >> 5, lane = threadIdx.x & 31;
    int id = blockIdx.x * 8 + warp;

    if (id < B_ANCH + NNEG) {
        const float* src;
        uint8_t* dst;
        if (id < B_ANCH) {
            src = anch + (size_t)id * D_DIM;  dst = g_a8 + (size_t)id * D_DIM;
        } else {
            int r = id - B_ANCH;
            src = neg + (size_t)r * D_DIM;    dst = g_n8 + (size_t)r * D_DIM;
        }
        const float4* s4 = (const float4*)src;
        float4 v0 = s4[lane], v1 = s4[lane + 32];
        float ss = v0.x*v0.x + v0.y*v0.y + v0.z*v0.z + v0.w*v0.w
                 + v1.x*v1.x + v1.y*v1.y + v1.z*v1.z + v1.w*v1.w;
        #pragma unroll
        for (int o = 16; o; o >>= 1) ss += __shfl_xor_sync(0xFFFFFFFFu, ss, o);
        float inv = 1.0f / fmaxf(sqrtf(ss), EPSN);
        uint32_t* d32 = (uint32_t*)dst;
        d32[lane]      = pack_e4m3_4(v0.x*inv, v0.y*inv, v0.z*inv, v0.w*inv);
        d32[lane + 32] = pack_e4m3_4(v1.x*inv, v1.y*inv, v1.z*inv, v1.w*inv);
    } else {
        int pid = id - (B_ANCH + NNEG);
        if (pid >= B_ANCH * P_POS) return;
        int b = pid >> 2;
        const float4* a4 = (const float4*)(anch + (size_t)b * D_DIM);
        const float4* p4 = (const float4*)(pos  + (size_t)pid * D_DIM);
        float4 a0 = a4[lane], a1 = a4[lane + 32];
        float4 p0 = p4[lane], p1 = p4[lane + 32];
        float dot = a0.x*p0.x + a0.y*p0.y + a0.z*p0.z + a0.w*p0.w
                  + a1.x*p1.x + a1.y*p1.y + a1.z*p1.z + a1.w*p1.w;
        float asq = a0.x*a0.x + a0.y*a0.y + a0.z*a0.z + a0.w*a0.w
                  + a1.x*a1.x + a1.y*a1.y + a1.z*a1.z + a1.w*a1.w;
        float psq = p0.x*p0.x + p0.y*p0.y + p0.z*p0.z + p0.w*p0.w
                  + p1.x*p1.x + p1.y*p1.y + p1.z*p1.z + p1.w*p1.w;
        #pragma unroll
        for (int o = 16; o; o >>= 1) {
            dot += __shfl_xor_sync(0xFFFFFFFFu, dot, o);
            asq += __shfl_xor_sync(0xFFFFFFFFu, asq, o);
            psq += __shfl_xor_sync(0xFFFFFFFFu, psq, o);
        }
        if (lane == 0) {
            float denom = fmaxf(sqrtf(asq), EPSN) * fmaxf(sqrtf(psq), EPSN);
            g_pos[pid] = dot / denom * INV_T;
        }
    }
}

// ============================================================
// Kernel 2: fp8 GEMM (R11 optimum) + last-CTA inline finalize
// ============================================================
extern __shared__ uint8_t smem_raw[];

__global__ void __launch_bounds__(256, 2)
gemm_lse_kernel(const int* __restrict__ counts, float* __restrict__ out) {
    uint8_t* sA = smem_raw;
    uint32_t sA_u = smem_u32(smem_raw);
    int tid = threadIdx.x;
    int w = tid >> 5, lane = tid & 31, g = lane >> 2, q = lane & 3;
    int m  = blockIdx.x & 15;
    int gp = blockIdx.x >> 4;
    int m0 = m * MT;
    int tstart = gp * 14 + min(gp, 4);      // 256 = 4*15 + 14*14
    int tcnt   = 14 + (gp < 4 ? 1 : 0);

    const __half2 k2h = __float2half2_rn(K2E);
    const __half2 c8h = __float2half2_rn(-SHIFT2);

    uint32_t ldsm_off = (uint32_t)((((lane >> 4) & 1) * 8 + (lane & 7)) * STR
                                   + ((lane >> 3) & 1) * 16);

    // ---- A tile (32KB) ----
    {
        const uint8_t* gA = g_a8 + (size_t)m0 * D_DIM;
        #pragma unroll
        for (int i = 0; i < 8; i++) {
            int c = tid + i * 256;
            int r = c >> 4, c16 = c & 15;
            cp_async16(sA_u + r * STR + c16 * 16, gA + (size_t)r * 256 + c16 * 16);
        }
    }
    CP_COMMIT();

    // ---- preload B tile 0 (32KB) ----
    {
        const uint8_t* gB = g_n8 + (size_t)tstart * NB * D_DIM;
        uint32_t sB_u = sA_u + A_BYTES;
        #pragma unroll
        for (int i = 0; i < 8; i++) {
            int c = tid + i * 256;
            int r = c >> 4, c16 = c & 15;
            cp_async16(sB_u + r * STR + c16 * 16, gB + (size_t)r * 256 + c16 * 16);
        }
    }
    CP_COMMIT();

    // ---- A fragments -> registers ----
    CP_WAIT(1);
    __syncthreads();
    uint32_t areg[32];
    {
        const uint8_t* r0 = sA + (size_t)(w * 16 + g) * STR;
        const uint8_t* r1 = r0 + 8 * STR;
        #pragma unroll
        for (int ks = 0; ks < 8; ks++) {
            int k0 = ks * 32;
            areg[4*ks+0] = *(const uint32_t*)(r0 + k0 + 4*q);
            areg[4*ks+1] = *(const uint32_t*)(r1 + k0 + 4*q);
            areg[4*ks+2] = *(const uint32_t*)(r0 + k0 + 16 + 4*q);
            areg[4*ks+3] = *(const uint32_t*)(r1 + k0 + 16 + 4*q);
        }
    }

    float rs0 = 0.0f, rs1 = 0.0f;

    for (int t = 0; t < tcnt; t++) {
        CP_WAIT(0);
        __syncthreads();

        if (t + 1 < tcnt) {
            const uint8_t* gB = g_n8 + (size_t)(tstart + t + 1) * NB * D_DIM;
            uint32_t sB_u = sA_u + A_BYTES + ((t + 1) & 1) * B_BYTES;
            #pragma unroll
            for (int i = 0; i < 8; i++) {
                int c = tid + i * 256;
                int r = c >> 4, c16 = c & 15;
                cp_async16(sB_u + r * STR + c16 * 16, gB + (size_t)r * 256 + c16 * 16);
            }
            CP_COMMIT();
        }

        uint32_t sB_base = sA_u + A_BYTES + (t & 1) * B_BYTES + ldsm_off;
        uint32_t acc[16][2];
        #pragma unroll
        for (int j = 0; j < 16; j++) { acc[j][0] = 0u; acc[j][1] = 0u; }

        #pragma unroll
        for (int ks = 0; ks < 8; ks++) {
            uint32_t kb = sB_base + ks * 32;
            #pragma unroll
            for (int jj = 0; jj < 8; jj++) {
                uint32_t b00, b01, b10, b11;
                ldsm_x4(b00, b01, b10, b11, kb + jj * (16 * STR));
                mma_fp8_h(acc[2*jj],     areg + 4*ks, b00, b01);
                mma_fp8_h(acc[2*jj + 1], areg + 4*ks, b10, b11);
            }
        }

        __half2 hs0 = __float2half2_rn(0.0f);
        __half2 hs1 = __float2half2_rn(0.0f);
        #pragma unroll
        for (int j = 0; j < 16; j++) {
            __half2 a0 = *(__half2*)&acc[j][0];
            __half2 a1 = *(__half2*)&acc[j][1];
            hs0 = __hadd2(hs0, h2exp2(__hfma2(a0, k2h, c8h)));
            hs1 = __hadd2(hs1, h2exp2(__hfma2(a1, k2h, c8h)));
        }
        float2 f0 = __half22float2(hs0);
        float2 f1 = __half22float2(hs1);
        rs0 += f0.x + f0.y;
        rs1 += f1.x + f1.y;
    }

    rs0 += __shfl_xor_sync(0xFFFFFFFFu, rs0, 1);
    rs0 += __shfl_xor_sync(0xFFFFFFFFu, rs0, 2);
    rs1 += __shfl_xor_sync(0xFFFFFFFFu, rs1, 1);
    rs1 += __shfl_xor_sync(0xFFFFFFFFu, rs1, 2);
    if (q == 0) {
        int row = m0 + w * 16 + g;
        g_part[(size_t)gp * B_ANCH + row]     = rs0;
        g_part[(size_t)gp * B_ANCH + row + 8] = rs1;
    }

    // ---- last-CTA-done inline finalize ----
    __threadfence();
    __syncthreads();
    __shared__ int s_last;
    if (tid == 0) s_last = (atomicAdd(&g_ctr, 1) == NCTAS - 1) ? 1 : 0;
    __syncthreads();
    if (!s_last) return;

    __threadfence();   // acquire all partials
    __shared__ float red[256];
    float local = 0.0f;
    #pragma unroll
    for (int bb = 0; bb < 8; bb++) {
        int b = tid + bb * 256;
        float s = 0.0f;
        #pragma unroll
        for (int c = 0; c < NGRP; c++) s += g_part[(size_t)c * B_ANCH + b];
        float lse = 5.545177444479562f + logf(s);    // 8*ln2 + log(s)
        int cnt = counts[b];
        float ps[4];
        #pragma unroll
        for (int j = 0; j < 4; j++) ps[j] = g_pos[b * 4 + j];

        #pragma unroll
        for (int j = 0; j < 4; j++) {
            if (j < cnt) {
                float mx = fmaxf(ps[j], lse);
                local += mx + log1pf(expf(fminf(ps[j], lse) - mx)) - ps[j];
            }
        }
        float mx = fmaxf(fmaxf(ps[0], ps[1]), fmaxf(ps[2], ps[3]));
        float e0 = expf(ps[0] - mx), e1 = expf(ps[1] - mx);
        float e2 = expf(ps[2] - mx), e3 = expf(ps[3] - mx);
        float wps = (e0*ps[0] + e1*ps[1] + e2*ps[2] + e3*ps[3]) / (e0 + e1 + e2 + e3);
        if (cnt > 1) {
            float m2 = fmaxf(wps, lse);
            local += ALPHA * (m2 + log1pf(expf(fminf(wps, lse) - m2)) - wps);
        }
    }
    red[tid] = local;
    __syncthreads();
    #pragma unroll
    for (int o = 128; o; o >>= 1) {
        if (tid < o) red[tid] += red[tid + o];
        __syncthreads();
    }
    if (tid == 0) {
        out[0] = red[0] / (float)B_ANCH;
        g_ctr = 0;                         // reset for next graph replay
    }
}

// ============================================================
extern "C" void kernel_launch(void* const* d_in, const int* in_sizes, int n_in,
                              void* d_out, int out_size) {
    const float* anch   = (const float*)d_in[0];
    const float* pos    = (const float*)d_in[1];
    const float* neg    = (const float*)d_in[2];
    const int*   counts = (const int*)d_in[3];
    float* out = (float*)d_out;

    cudaFuncSetAttribute(gemm_lse_kernel,
                         cudaFuncAttributeMaxDynamicSharedMemorySize, SMEM_TOTAL);

    prep_kernel<<<(B_ANCH + NNEG + B_ANCH * P_POS) / 8, 256>>>(anch, pos, neg);
    gemm_lse_kernel<<<NCTAS, 256, SMEM_TOTAL>>>(counts, out);
}

// round 15
// speedup vs baseline: 1.0323x; 1.0323x over previous
#include <cuda_runtime.h>
#include <cuda_fp16.h>
#include <cstdint>

#define B_ANCH 2048
#define P_POS  4
#define D_DIM  256            // K
#define NNEG   32768
#define ALPHA  0.1f
#define EPSN   1e-12f
#define INV_T  20.0f          // 1/temperature
#define K2E    28.85390081777927f   // 20 * log2(e)
#define SHIFT2 8.0f                 // sum exp2(logit2 - 8)

#define MT     128            // anchors per CTA
#define NB     128            // negatives per tile
#define MBLKS  (B_ANCH / MT)  // 16
#define NGRP   18             // grid 16*18 = 288 CTAs
#define STR    272            // smem row stride bytes

#define A_BYTES (MT * STR)          // 34816
#define B_BYTES (NB * STR)          // 34816
#define SMEM_TOTAL (A_BYTES + 2 * B_BYTES)   // 104448 -> occ 2

// ---- scratch ----
__device__ uint8_t g_a8[B_ANCH * D_DIM];      // e4m3
__device__ uint8_t g_n8[NNEG * D_DIM];        // e4m3
__device__ float g_pos[B_ANCH * P_POS];
__device__ float g_part[NGRP * B_ANCH];       // [gp][anchor]

// ================= helpers =================
__device__ __forceinline__ uint32_t smem_u32(const void* p) {
    uint32_t a;
    asm("{ .reg .u64 t; cvta.to.shared.u64 t, %1; cvt.u32.u64 %0, t; }" : "=r"(a) : "l"(p));
    return a;
}
__device__ __forceinline__ void cp_async16(uint32_t dst, const void* src) {
    asm volatile("cp.async.cg.shared.global [%0], [%1], 16;" :: "r"(dst), "l"(src) : "memory");
}
#define CP_COMMIT() asm volatile("cp.async.commit_group;" ::: "memory")
#define CP_WAIT(n)  asm volatile("cp.async.wait_group %0;" :: "n"(n) : "memory")

__device__ __forceinline__ uint32_t pack_e4m3_4(float x, float y, float z, float w) {
    uint16_t lo, hi;
    asm("cvt.rn.satfinite.e4m3x2.f32 %0, %1, %2;" : "=h"(lo) : "f"(y), "f"(x));
    asm("cvt.rn.satfinite.e4m3x2.f32 %0, %1, %2;" : "=h"(hi) : "f"(w), "f"(z));
    return (uint32_t)lo | ((uint32_t)hi << 16);
}

__device__ __forceinline__ void mma_fp8_h(uint32_t* c, const uint32_t* a,
                                          uint32_t b0, uint32_t b1) {
    asm volatile(
        "mma.sync.aligned.m16n8k32.row.col.f16.e4m3.e4m3.f16 "
        "{%0,%1}, {%2,%3,%4,%5}, {%6,%7}, {%0,%1};\n"
        : "+r"(c[0]), "+r"(c[1])
        : "r"(a[0]), "r"(a[1]), "r"(a[2]), "r"(a[3]), "r"(b0), "r"(b1));
}

__device__ __forceinline__ void ldsm_x4(uint32_t& r0, uint32_t& r1,
                                        uint32_t& r2, uint32_t& r3, uint32_t a) {
    asm volatile("ldmatrix.sync.aligned.m8n8.x4.shared.b16 {%0,%1,%2,%3}, [%4];"
                 : "=r"(r0), "=r"(r1), "=r"(r2), "=r"(r3) : "r"(a));
}

// ============================================================
// Kernel 1: fused prep — normalize (8B coalesced stores) + pos
// tasks: [0, B+N) normalize, [B+N, B+N+B*P) pos
// ============================================================
__global__ void prep_kernel(const float* __restrict__ anch,
                            const float* __restrict__ pos,
                            const float* __restrict__ neg) {
    int warp = threadIdx.x >> 5, lane = threadIdx.x & 31;
    int id = blockIdx.x * 8 + warp;

    if (id < B_ANCH + NNEG) {
        const float* src;
        uint8_t* dst;
        if (id < B_ANCH) {
            src = anch + (size_t)id * D_DIM;  dst = g_a8 + (size_t)id * D_DIM;
        } else {
            int r = id - B_ANCH;
            src = neg + (size_t)r * D_DIM;    dst = g_n8 + (size_t)r * D_DIM;
        }
        const float4* s4 = (const float4*)src;
        float4 v0 = s4[2 * lane], v1 = s4[2 * lane + 1];    // 8 consecutive floats
        float ss = v0.x*v0.x + v0.y*v0.y + v0.z*v0.z + v0.w*v0.w
                 + v1.x*v1.x + v1.y*v1.y + v1.z*v1.z + v1.w*v1.w;
        #pragma unroll
        for (int o = 16; o; o >>= 1) ss += __shfl_xor_sync(0xFFFFFFFFu, ss, o);
        float inv = 1.0f / fmaxf(sqrtf(ss), EPSN);
        uint2 outv;
        outv.x = pack_e4m3_4(v0.x*inv, v0.y*inv, v0.z*inv, v0.w*inv);
        outv.y = pack_e4m3_4(v1.x*inv, v1.y*inv, v1.z*inv, v1.w*inv);
        ((uint2*)dst)[lane] = outv;                          // one 8B coalesced store
    } else {
        int pid = id - (B_ANCH + NNEG);
        if (pid >= B_ANCH * P_POS) return;
        int b = pid >> 2;
        const float4* a4 = (const float4*)(anch + (size_t)b * D_DIM);
        const float4* p4 = (const float4*)(pos  + (size_t)pid * D_DIM);
        float4 a0 = a4[lane], a1 = a4[lane + 32];
        float4 p0 = p4[lane], p1 = p4[lane + 32];
        float dot = a0.x*p0.x + a0.y*p0.y + a0.z*p0.z + a0.w*p0.w
                  + a1.x*p1.x + a1.y*p1.y + a1.z*p1.z + a1.w*p1.w;
        float asq = a0.x*a0.x + a0.y*a0.y + a0.z*a0.z + a0.w*a0.w
                  + a1.x*a1.x + a1.y*a1.y + a1.z*a1.z + a1.w*a1.w;
        float psq = p0.x*p0.x + p0.y*p0.y + p0.z*p0.z + p0.w*p0.w
                  + p1.x*p1.x + p1.y*p1.y + p1.z*p1.z + p1.w*p1.w;
        #pragma unroll
        for (int o = 16; o; o >>= 1) {
            dot += __shfl_xor_sync(0xFFFFFFFFu, dot, o);
            asq += __shfl_xor_sync(0xFFFFFFFFu, asq, o);
            psq += __shfl_xor_sync(0xFFFFFFFFu, psq, o);
        }
        if (lane == 0) {
            float denom = fmaxf(sqrtf(asq), EPSN) * fmaxf(sqrtf(psq), EPSN);
            g_pos[pid] = dot / denom * INV_T;
        }
    }
}

// ============================================================
// Kernel 2: fp8 mma.sync GEMM (128x128 tiles), 2-stage cp.async
// (R11 optimum + hoisted prefetch offsets)
// ============================================================
extern __shared__ uint8_t smem_raw[];

__global__ void __launch_bounds__(256, 2) gemm_lse_kernel() {
    uint8_t* sA = smem_raw;
    uint32_t sA_u = smem_u32(smem_raw);
    int tid = threadIdx.x;
    int w = tid >> 5, lane = tid & 31, g = lane >> 2, q = lane & 3;
    int m  = blockIdx.x & 15;
    int gp = blockIdx.x >> 4;
    int m0 = m * MT;
    int tstart = gp * 14 + min(gp, 4);      // 256 = 4*15 + 14*14
    int tcnt   = 14 + (gp < 4 ? 1 : 0);

    const __half2 k2h = __float2half2_rn(K2E);
    const __half2 c8h = __float2half2_rn(-SHIFT2);

    uint32_t ldsm_off = (uint32_t)((((lane >> 4) & 1) * 8 + (lane & 7)) * STR
                                   + ((lane >> 3) & 1) * 16);

    // hoisted per-thread copy offsets: thread covers rows r0c+16i, 16B chunk c16
    int r0c = tid >> 4, c16b = (tid & 15) * 16;
    uint32_t sm_off = (uint32_t)(r0c * STR + c16b);     // smem offset within a buffer
    uint32_t gl_off = (uint32_t)(r0c * 256 + c16b);     // global offset within a tile

    // ---- A tile (32KB) ----
    {
        const uint8_t* gA = g_a8 + (size_t)m0 * D_DIM + gl_off;
        #pragma unroll
        for (int i = 0; i < 8; i++)
            cp_async16(sA_u + sm_off + i * (16 * STR), gA + i * (16 * 256));
    }
    CP_COMMIT();

    // ---- preload B tile 0 (32KB) ----
    {
        const uint8_t* gB = g_n8 + (size_t)tstart * NB * D_DIM + gl_off;
        uint32_t sB_u = sA_u + A_BYTES + sm_off;
        #pragma unroll
        for (int i = 0; i < 8; i++)
            cp_async16(sB_u + i * (16 * STR), gB + i * (16 * 256));
    }
    CP_COMMIT();

    // ---- A fragments -> registers ----
    CP_WAIT(1);
    __syncthreads();
    uint32_t areg[32];
    {
        const uint8_t* r0 = sA + (size_t)(w * 16 + g) * STR;
        const uint8_t* r1 = r0 + 8 * STR;
        #pragma unroll
        for (int ks = 0; ks < 8; ks++) {
            int k0 = ks * 32;
            areg[4*ks+0] = *(const uint32_t*)(r0 + k0 + 4*q);
            areg[4*ks+1] = *(const uint32_t*)(r1 + k0 + 4*q);
            areg[4*ks+2] = *(const uint32_t*)(r0 + k0 + 16 + 4*q);
            areg[4*ks+3] = *(const uint32_t*)(r1 + k0 + 16 + 4*q);
        }
    }

    float rs0 = 0.0f, rs1 = 0.0f;

    for (int t = 0; t < tcnt; t++) {
        CP_WAIT(0);
        __syncthreads();

        if (t + 1 < tcnt) {
            const uint8_t* gB = g_n8 + (size_t)(tstart + t + 1) * NB * D_DIM + gl_off;
            uint32_t sB_u = sA_u + A_BYTES + ((t + 1) & 1) * B_BYTES + sm_off;
            #pragma unroll
            for (int i = 0; i < 8; i++)
                cp_async16(sB_u + i * (16 * STR), gB + i * (16 * 256));
            CP_COMMIT();
        }

        uint32_t sB_base = sA_u + A_BYTES + (t & 1) * B_BYTES + ldsm_off;
        uint32_t acc[16][2];
        #pragma unroll
        for (int j = 0; j < 16; j++) { acc[j][0] = 0u; acc[j][1] = 0u; }

        #pragma unroll
        for (int ks = 0; ks < 8; ks++) {
            uint32_t kb = sB_base + ks * 32;
            #pragma unroll
            for (int jj = 0; jj < 8; jj++) {
                uint32_t b00, b01, b10, b11;
                ldsm_x4(b00, b01, b10, b11, kb + jj * (16 * STR));
                mma_fp8_h(acc[2*jj],     areg + 4*ks, b00, b01);
                mma_fp8_h(acc[2*jj + 1], areg + 4*ks, b10, b11);
            }
        }

        __half2 hs0 = __float2half2_rn(0.0f);
        __half2 hs1 = __float2half2_rn(0.0f);
        #pragma unroll
        for (int j = 0; j < 16; j++) {
            __half2 a0 = *(__half2*)&acc[j][0];
            __half2 a1 = *(__half2*)&acc[j][1];
            hs0 = __hadd2(hs0, h2exp2(__hfma2(a0, k2h, c8h)));
            hs1 = __hadd2(hs1, h2exp2(__hfma2(a1, k2h, c8h)));
        }
        float2 f0 = __half22float2(hs0);
        float2 f1 = __half22float2(hs1);
        rs0 += f0.x + f0.y;
        rs1 += f1.x + f1.y;
    }

    rs0 += __shfl_xor_sync(0xFFFFFFFFu, rs0, 1);
    rs0 += __shfl_xor_sync(0xFFFFFFFFu, rs0, 2);
    rs1 += __shfl_xor_sync(0xFFFFFFFFu, rs1, 1);
    rs1 += __shfl_xor_sync(0xFFFFFFFFu, rs1, 2);
    if (q == 0) {
        int row = m0 + w * 16 + g;
        g_part[(size_t)gp * B_ANCH + row]     = rs0;
        g_part[(size_t)gp * B_ANCH + row + 8] = rs1;
    }
}

// ============================================================
// Kernel 3: finalize — single block, 1024 threads, 2 anchors each
// lse = 8*ln2 + log(sum)
// ============================================================
__global__ void finalize_kernel(const int* __restrict__ counts,
                                float* __restrict__ out) {
    __shared__ float red[1024];
    int tid = threadIdx.x;
    float local = 0.0f;

    #pragma unroll
    for (int bb = 0; bb < 2; bb++) {
        int b = tid + bb * 1024;
        float s = 0.0f;
        #pragma unroll
        for (int c = 0; c < NGRP; c++) s += g_part[(size_t)c * B_ANCH + b];
        float lse = 5.545177444479562f + logf(s);
        int cnt = counts[b];
        float ps[4];
        #pragma unroll
        for (int j = 0; j < 4; j++) ps[j] = g_pos[b * 4 + j];

        #pragma unroll
        for (int j = 0; j < 4; j++) {
            if (j < cnt) {
                float mx = fmaxf(ps[j], lse);
                local += mx + log1pf(expf(fminf(ps[j], lse) - mx)) - ps[j];
            }
        }
        float mx = fmaxf(fmaxf(ps[0], ps[1]), fmaxf(ps[2], ps[3]));
        float e0 = expf(ps[0] - mx), e1 = expf(ps[1] - mx);
        float e2 = expf(ps[2] - mx), e3 = expf(ps[3] - mx);
        float wps = (e0*ps[0] + e1*ps[1] + e2*ps[2] + e3*ps[3]) / (e0 + e1 + e2 + e3);
        if (cnt > 1) {
            float m2 = fmaxf(wps, lse);
            local += ALPHA * (m2 + log1pf(expf(fminf(wps, lse) - m2)) - wps);
        }
    }

    red[tid] = local;
    __syncthreads();
    #pragma unroll
    for (int o = 512; o; o >>= 1) {
        if (tid < o) red[tid] += red[tid + o];
        __syncthreads();
    }
    if (tid == 0) out[0] = red[0] / (float)B_ANCH;
}

// ============================================================
extern "C" void kernel_launch(void* const* d_in, const int* in_sizes, int n_in,
                              void* d_out, int out_size) {
    const float* anch   = (const float*)d_in[0];
    const float* pos    = (const float*)d_in[1];
    const float* neg    = (const float*)d_in[2];
    const int*   counts = (const int*)d_in[3];
    float* out = (float*)d_out;

    cudaFuncSetAttribute(gemm_lse_kernel,
                         cudaFuncAttributeMaxDynamicSharedMemorySize, SMEM_TOTAL);

    prep_kernel<<<(B_ANCH + NNEG + B_ANCH * P_POS) / 8, 256>>>(anch, pos, neg);
    gemm_lse_kernel<<<MBLKS * NGRP, 256, SMEM_TOTAL>>>();
    finalize_kernel<<<1, 1024>>>(counts, out);
}